// round 15
// baseline (speedup 1.0000x reference)
#include <cuda_runtime.h>
#include <math.h>
#include <stdint.h>

// Problem constants
#define B_  2
#define T_  2048
#define C_  1024
#define H_  16
#define D_  64
#define BH_ (B_ * H_)       // 32
#define M_  (B_ * T_)       // 4096

// Scratch (device globals — no allocation allowed)
__device__ float g_q[BH_ * T_ * D_];     // [bh][t][d]
__device__ float g_k[BH_ * T_ * D_];
__device__ float g_v[BH_ * T_ * D_];
__device__ float g_ctx[M_ * C_];         // [b*t][h*64+d]

// Work-queue counters: [0]=qkv, [1]=attn, [2]=out
__device__ unsigned g_ctr[4];

__global__ void reset_ctrs() {
    g_ctr[0] = 0; g_ctr[1] = 0; g_ctr[2] = 0; g_ctr[3] = 0;
}

// ===========================================================================
// tf32 warp MMA helpers (sm_80+ baseline — valid on plain sm_103 target)
// ===========================================================================
__device__ __forceinline__ uint32_t f2tf32(float f) {
    uint32_t u;
    asm("cvt.rna.tf32.f32 %0, %1;" : "=r"(u) : "f"(f));
    return u;
}

__device__ __forceinline__ void mma_tf32(float* c, const uint32_t* a,
                                         const uint32_t* b) {
    asm volatile(
        "mma.sync.aligned.m16n8k8.row.col.f32.tf32.tf32.f32 "
        "{%0,%1,%2,%3}, {%4,%5,%6,%7}, {%8,%9}, {%0,%1,%2,%3};"
        : "+f"(c[0]), "+f"(c[1]), "+f"(c[2]), "+f"(c[3])
        : "r"(a[0]), "r"(a[1]), "r"(a[2]), "r"(a[3]), "r"(b[0]), "r"(b[1]));
}

#define GRID_P (2 * 148)   // persistent grid: 2 CTAs/SM x 148 SMs

// ===========================================================================
// qkv GEMM, persistent work-queue version of the R10 kernel (math identical).
// 768 tiles of 128x128 over K=1024.  A = x, scatter into g_q/g_k/g_v.
// ===========================================================================
#define APAD 36
#define BPAD 136
#define QKV_NT (24 * 32)   // 24 n-tiles x 32 m-tiles

__global__ __launch_bounds__(256, 2) void qkv_gemm(const float* __restrict__ Ain,
                                                   const float* __restrict__ Bw,
                                                   const float* __restrict__ bias) {
    __shared__ uint32_t As[128 * APAD];
    __shared__ uint32_t Bs[32 * BPAD];
    __shared__ unsigned s_item;

    const int tid = threadIdx.x;
    const int wid = tid >> 5, lane = tid & 31;
    const int warp_m = (wid >> 2) * 64;
    const int warp_n = (wid & 3) * 32;
    const int g = lane >> 2, t = lane & 3;
    const int N = 3 * C_;

    for (;;) {
        if (tid == 0) s_item = atomicAdd(&g_ctr[0], 1u);
        __syncthreads();
        const unsigned item = s_item;
        if (item >= QKV_NT) break;
        const int bn = (int)(item % 24) * 128;
        const int bm = (int)(item / 24) * 128;

        float acc[4][4][4];
#pragma unroll
        for (int mf = 0; mf < 4; mf++)
#pragma unroll
            for (int nf = 0; nf < 4; nf++)
#pragma unroll
                for (int r = 0; r < 4; r++) acc[mf][nf][r] = 0.f;

        for (int k0 = 0; k0 < C_; k0 += 32) {
            __syncthreads();
#pragma unroll
            for (int r = 0; r < 4; r++) {
                int idx = tid + r * 256;
                int m = idx >> 3, kk = idx & 7;
                float4 v = *(const float4*)(Ain + (size_t)(bm + m) * C_ + k0 + kk * 4);
                uint32_t* d = &As[m * APAD + kk * 4];
                d[0] = f2tf32(v.x); d[1] = f2tf32(v.y);
                d[2] = f2tf32(v.z); d[3] = f2tf32(v.w);
            }
#pragma unroll
            for (int r = 0; r < 4; r++) {
                int idx = tid + r * 256;
                int k = idx >> 5, n4 = idx & 31;
                float4 v = *(const float4*)(Bw + (size_t)(k0 + k) * N + bn + n4 * 4);
                uint32_t* d = &Bs[k * BPAD + n4 * 4];
                d[0] = f2tf32(v.x); d[1] = f2tf32(v.y);
                d[2] = f2tf32(v.z); d[3] = f2tf32(v.w);
            }
            __syncthreads();

#pragma unroll
            for (int ks = 0; ks < 4; ks++) {
                const int kb = ks * 8;
                uint32_t af[4][4], bf[4][2];
#pragma unroll
                for (int mf = 0; mf < 4; mf++) {
                    const uint32_t* ap = &As[(warp_m + mf * 16 + g) * APAD + kb + t];
                    af[mf][0] = ap[0];
                    af[mf][1] = ap[8 * APAD];
                    af[mf][2] = ap[4];
                    af[mf][3] = ap[8 * APAD + 4];
                }
#pragma unroll
                for (int nf = 0; nf < 4; nf++) {
                    const uint32_t* bp = &Bs[(kb + t) * BPAD + warp_n + nf * 8 + g];
                    bf[nf][0] = bp[0];
                    bf[nf][1] = bp[4 * BPAD];
                }
#pragma unroll
                for (int mf = 0; mf < 4; mf++)
#pragma unroll
                    for (int nf = 0; nf < 4; nf++)
                        mma_tf32(acc[mf][nf], af[mf], bf[nf]);
            }
        }

#pragma unroll
        for (int mf = 0; mf < 4; mf++) {
#pragma unroll
            for (int nf = 0; nf < 4; nf++) {
                const int n = bn + warp_n + nf * 8 + 2 * t;
                const float b0v = bias[n], b1v = bias[n + 1];
#pragma unroll
                for (int half = 0; half < 2; half++) {
                    const int m = bm + warp_m + mf * 16 + g + half * 8;
                    float v0 = acc[mf][nf][half * 2 + 0] + b0v;
                    float v1 = acc[mf][nf][half * 2 + 1] + b1v;
                    int which = n >> 10;
                    int rem = n & 1023;
                    int h = rem >> 6, d = rem & 63;
                    int bi = m >> 11, tt = m & (T_ - 1);
                    float* dst = (which == 0) ? g_q : (which == 1) ? g_k : g_v;
                    *(float2*)&dst[(size_t)(((bi << 4) + h) * T_ + tt) * D_ + d] =
                        make_float2(v0, v1);
                }
            }
        }
        __syncthreads();   // all warps done before tid0 overwrites s_item
    }
}

// ===========================================================================
// Out GEMM, persistent, 128x64 tiles (512 items > 296 workers so the queue
// packs). Warp tile 64x16 (nf<2). BPAD2=72: b-frag bank=(8t+g)+c, 32 distinct.
// Per-output math identical to before (same K order, same bias add).
// ===========================================================================
#define BPAD2 72
#define OUT_NT (16 * 32)   // 16 n-tiles(64) x 32 m-tiles(128)

__global__ __launch_bounds__(256, 2) void out_gemm(const float* __restrict__ Bw,
                                                   const float* __restrict__ bias,
                                                   float* __restrict__ Out) {
    __shared__ uint32_t As[128 * APAD];
    __shared__ uint32_t Bs[32 * BPAD2];
    __shared__ unsigned s_item;

    const int tid = threadIdx.x;
    const int wid = tid >> 5, lane = tid & 31;
    const int warp_m = (wid >> 2) * 64;
    const int warp_n = (wid & 3) * 16;
    const int g = lane >> 2, t = lane & 3;
    const int N = C_;

    for (;;) {
        if (tid == 0) s_item = atomicAdd(&g_ctr[2], 1u);
        __syncthreads();
        const unsigned item = s_item;
        if (item >= OUT_NT) break;
        const int bn = (int)(item & 15) * 64;
        const int bm = (int)(item >> 4) * 128;

        float acc[4][2][4];
#pragma unroll
        for (int mf = 0; mf < 4; mf++)
#pragma unroll
            for (int nf = 0; nf < 2; nf++)
#pragma unroll
                for (int r = 0; r < 4; r++) acc[mf][nf][r] = 0.f;

        for (int k0 = 0; k0 < C_; k0 += 32) {
            __syncthreads();
#pragma unroll
            for (int r = 0; r < 4; r++) {
                int idx = tid + r * 256;
                int m = idx >> 3, kk = idx & 7;
                float4 v = *(const float4*)((const float*)g_ctx +
                                            (size_t)(bm + m) * C_ + k0 + kk * 4);
                uint32_t* d = &As[m * APAD + kk * 4];
                d[0] = f2tf32(v.x); d[1] = f2tf32(v.y);
                d[2] = f2tf32(v.z); d[3] = f2tf32(v.w);
            }
            // B tile 32k x 64n: 512 words/thread-pass -> 2 float4 per thread
#pragma unroll
            for (int r = 0; r < 2; r++) {
                int idx = tid + r * 256;
                int k = idx >> 4, n4 = idx & 15;
                float4 v = *(const float4*)(Bw + (size_t)(k0 + k) * N + bn + n4 * 4);
                uint32_t* d = &Bs[k * BPAD2 + n4 * 4];
                d[0] = f2tf32(v.x); d[1] = f2tf32(v.y);
                d[2] = f2tf32(v.z); d[3] = f2tf32(v.w);
            }
            __syncthreads();

#pragma unroll
            for (int ks = 0; ks < 4; ks++) {
                const int kb = ks * 8;
                uint32_t af[4][4], bf[2][2];
#pragma unroll
                for (int mf = 0; mf < 4; mf++) {
                    const uint32_t* ap = &As[(warp_m + mf * 16 + g) * APAD + kb + t];
                    af[mf][0] = ap[0];
                    af[mf][1] = ap[8 * APAD];
                    af[mf][2] = ap[4];
                    af[mf][3] = ap[8 * APAD + 4];
                }
#pragma unroll
                for (int nf = 0; nf < 2; nf++) {
                    const uint32_t* bp = &Bs[(kb + t) * BPAD2 + warp_n + nf * 8 + g];
                    bf[nf][0] = bp[0];
                    bf[nf][1] = bp[4 * BPAD2];
                }
#pragma unroll
                for (int mf = 0; mf < 4; mf++)
#pragma unroll
                    for (int nf = 0; nf < 2; nf++)
                        mma_tf32(acc[mf][nf], af[mf], bf[nf]);
            }
        }

#pragma unroll
        for (int mf = 0; mf < 4; mf++) {
#pragma unroll
            for (int nf = 0; nf < 2; nf++) {
                const int n = bn + warp_n + nf * 8 + 2 * t;
                const float b0v = bias[n], b1v = bias[n + 1];
#pragma unroll
                for (int half = 0; half < 2; half++) {
                    const int m = bm + warp_m + mf * 16 + g + half * 8;
                    *(float2*)&Out[(size_t)m * N + n] =
                        make_float2(acc[mf][nf][half * 2 + 0] + b0v,
                                    acc[mf][nf][half * 2 + 1] + b1v);
                }
            }
        }
        __syncthreads();
    }
}

// ===========================================================================
// tf32 mma.sync flash attention — R10 body (proven), persistent work queue.
// 512 items of (q-tile 128, bh).  Single-buffered K/V, two syncs per tile.
// ===========================================================================
#define QK_PAD 68
#define V_PAD  72
#define ATTN_NT (16 * 32)   // 16 q-tiles x 32 bh
#define ATTN_SMEM_BYTES ((128 * QK_PAD + 64 * QK_PAD + 64 * V_PAD) * 4)

__global__ __launch_bounds__(256, 2) void attn_mma() {
    extern __shared__ uint32_t smu[];
    uint32_t* Qs = smu;                               // [128][68]
    uint32_t* Ks = smu + 128 * QK_PAD;                // [64][68]
    uint32_t* Vs = smu + 128 * QK_PAD + 64 * QK_PAD;  // [64][72]
    __shared__ unsigned s_item;

    const int tid = threadIdx.x;
    const int wid = tid >> 5, lane = tid & 31;
    const int g = lane >> 2, t = lane & 3;
    const int qrow = wid * 16;

    for (;;) {
        if (tid == 0) s_item = atomicAdd(&g_ctr[1], 1u);
        __syncthreads();    // broadcast; also: all warps done with prior item
        const unsigned item = s_item;
        if (item >= ATTN_NT) break;
        const int q0 = (int)(item & 15) * 128;
        const int bh = (int)(item >> 4);

        const float* Qg = g_q + (size_t)bh * T_ * D_;
        const float* Kg = g_k + (size_t)bh * T_ * D_;
        const float* Vg = g_v + (size_t)bh * T_ * D_;

        // Load Q tile (scaled by 1/8, tf32).
#pragma unroll
        for (int r = 0; r < 8; r++) {
            int idx = tid + r * 256;
            int m = idx >> 4, c4 = idx & 15;
            float4 v = *(const float4*)(Qg + (size_t)(q0 + m) * D_ + c4 * 4);
            *(uint4*)&Qs[m * QK_PAD + c4 * 4] =
                make_uint4(f2tf32(v.x * 0.125f), f2tf32(v.y * 0.125f),
                           f2tf32(v.z * 0.125f), f2tf32(v.w * 0.125f));
        }

        float m_i[2] = {-1e30f, -1e30f};
        float l_i[2] = {0.f, 0.f};
        float o[8][4];
#pragma unroll
        for (int nb = 0; nb < 8; nb++)
#pragma unroll
            for (int r = 0; r < 4; r++) o[nb][r] = 0.f;

        for (int kt = 0; kt < T_; kt += 64) {
            __syncthreads();   // prior tile consumed (and Q stores on iter 0)

#pragma unroll
            for (int r = 0; r < 4; r++) {
                int idx = tid + r * 256;
                int s = idx >> 4, c4 = idx & 15;
                float4 v = *(const float4*)(Kg + (size_t)(kt + s) * D_ + c4 * 4);
                *(uint4*)&Ks[s * QK_PAD + c4 * 4] =
                    make_uint4(f2tf32(v.x), f2tf32(v.y), f2tf32(v.z), f2tf32(v.w));
            }
#pragma unroll
            for (int r = 0; r < 4; r++) {
                int idx = tid + r * 256;
                int s = idx >> 4, c4 = idx & 15;
                float4 v = *(const float4*)(Vg + (size_t)(kt + s) * D_ + c4 * 4);
                *(uint4*)&Vs[s * V_PAD + c4 * 4] =
                    make_uint4(f2tf32(v.x), f2tf32(v.y), f2tf32(v.z), f2tf32(v.w));
            }
            __syncthreads();

            // S = (Q/8) @ K^T
            float sfr[8][4];
#pragma unroll
            for (int nb = 0; nb < 8; nb++)
#pragma unroll
                for (int r = 0; r < 4; r++) sfr[nb][r] = 0.f;

#pragma unroll
            for (int ks = 0; ks < 8; ks++) {
                uint32_t af[4];
                const uint32_t* ap = &Qs[(qrow + g) * QK_PAD + ks * 8 + t];
                af[0] = ap[0];
                af[1] = ap[8 * QK_PAD];
                af[2] = ap[4];
                af[3] = ap[8 * QK_PAD + 4];
#pragma unroll
                for (int nb = 0; nb < 8; nb++) {
                    uint32_t bf[2];
                    const uint32_t* bp = &Ks[(nb * 8 + g) * QK_PAD + ks * 8 + t];
                    bf[0] = bp[0];
                    bf[1] = bp[4];
                    mma_tf32(sfr[nb], af, bf);
                }
            }

            // Online softmax per row-half (rows g, g+8), in-place exp on sfr.
#pragma unroll
            for (int half = 0; half < 2; half++) {
                const int h2 = half * 2;
                float mx = sfr[0][h2];
#pragma unroll
                for (int nb = 0; nb < 8; nb++) {
                    mx = fmaxf(mx, sfr[nb][h2]);
                    mx = fmaxf(mx, sfr[nb][h2 + 1]);
                }
                mx = fmaxf(mx, __shfl_xor_sync(0xffffffffu, mx, 1));
                mx = fmaxf(mx, __shfl_xor_sync(0xffffffffu, mx, 2));
                float mnew = fmaxf(m_i[half], mx);
                float corr = __expf(m_i[half] - mnew);
                m_i[half] = mnew;
                float ps = 0.f;
#pragma unroll
                for (int nb = 0; nb < 8; nb++) {
                    float p0 = __expf(sfr[nb][h2] - mnew);
                    float p1 = __expf(sfr[nb][h2 + 1] - mnew);
                    sfr[nb][h2] = p0;
                    sfr[nb][h2 + 1] = p1;
                    ps += p0 + p1;
                }
                ps += __shfl_xor_sync(0xffffffffu, ps, 1);
                ps += __shfl_xor_sync(0xffffffffu, ps, 2);
                l_i[half] = l_i[half] * corr + ps;
#pragma unroll
                for (int nb = 0; nb < 8; nb++) {
                    o[nb][h2] *= corr;
                    o[nb][h2 + 1] *= corr;
                }
            }

            // O += P @ V
            const int src0 = (lane & ~3) | (t >> 1);
#pragma unroll
            for (int ks = 0; ks < 8; ks++) {
                float x00 = __shfl_sync(0xffffffffu, sfr[ks][0], src0);
                float x01 = __shfl_sync(0xffffffffu, sfr[ks][1], src0);
                float x20 = __shfl_sync(0xffffffffu, sfr[ks][0], src0 + 2);
                float x21 = __shfl_sync(0xffffffffu, sfr[ks][1], src0 + 2);
                float x10 = __shfl_sync(0xffffffffu, sfr[ks][2], src0);
                float x11 = __shfl_sync(0xffffffffu, sfr[ks][3], src0);
                float x30 = __shfl_sync(0xffffffffu, sfr[ks][2], src0 + 2);
                float x31 = __shfl_sync(0xffffffffu, sfr[ks][3], src0 + 2);
                uint32_t af[4];
                af[0] = f2tf32((t & 1) ? x01 : x00);
                af[1] = f2tf32((t & 1) ? x11 : x10);
                af[2] = f2tf32((t & 1) ? x21 : x20);
                af[3] = f2tf32((t & 1) ? x31 : x30);
#pragma unroll
                for (int db = 0; db < 8; db++) {
                    uint32_t bf[2];
                    const uint32_t* bp = &Vs[(ks * 8 + t) * V_PAD + db * 8 + g];
                    bf[0] = bp[0];
                    bf[1] = bp[4 * V_PAD];
                    mma_tf32(o[db], af, bf);
                }
            }
        }

        // Normalize and write ctx[b][t][h*64+d]
        const int bi = bh >> 4, h = bh & 15;
        const float inv0 = 1.0f / l_i[0];
        const float inv1 = 1.0f / l_i[1];
#pragma unroll
        for (int db = 0; db < 8; db++) {
            const int d = db * 8 + 2 * t;
#pragma unroll
            for (int half = 0; half < 2; half++) {
                const float inv = half ? inv1 : inv0;
                const int tq = q0 + qrow + g + half * 8;
                float* dst = g_ctx + (size_t)(bi * T_ + tq) * C_ + h * D_ + d;
                *(float2*)dst = make_float2(o[db][half * 2] * inv,
                                            o[db][half * 2 + 1] * inv);
            }
        }
    }
}

// ---------------------------------------------------------------------------
// Launch
// ---------------------------------------------------------------------------
extern "C" void kernel_launch(void* const* d_in, const int* in_sizes, int n_in,
                              void* d_out, int out_size) {
    const float* x     = (const float*)d_in[0];
    const float* W_qkv = (const float*)d_in[1];
    const float* b_qkv = (const float*)d_in[2];
    const float* W_out = (const float*)d_in[3];
    const float* b_out = (const float*)d_in[4];
    float* out = (float*)d_out;

    (void)in_sizes; (void)n_in; (void)out_size;

    cudaFuncSetAttribute(attn_mma, cudaFuncAttributeMaxDynamicSharedMemorySize,
                         ATTN_SMEM_BYTES);

    reset_ctrs<<<1, 1>>>();
    qkv_gemm<<<GRID_P, 256>>>(x, W_qkv, b_qkv);
    attn_mma<<<GRID_P, 256, ATTN_SMEM_BYTES>>>();
    out_gemm<<<GRID_P, 256>>>(W_out, b_out, out);
}

// round 17
// speedup vs baseline: 1.5812x; 1.5812x over previous
#include <cuda_runtime.h>
#include <cuda_fp16.h>
#include <math.h>
#include <stdint.h>

// Problem constants
#define B_  2
#define T_  2048
#define C_  1024
#define H_  16
#define D_  64
#define BH_ (B_ * H_)       // 32
#define M_  (B_ * T_)       // 4096

// Scratch (device globals — no allocation allowed)
__device__ float g_q[BH_ * T_ * D_];     // [bh][t][d]
__device__ float g_k[BH_ * T_ * D_];
__device__ float g_v[BH_ * T_ * D_];
__device__ float g_ctx[M_ * C_];         // [b*t][h*64+d]

// ===========================================================================
// fp16 mma.sync helpers (sm_80+ baseline — valid on plain sm_103 target)
// ===========================================================================
__device__ __forceinline__ uint32_t pack_h2(float lo, float hi) {
    __half2 h = __floats2half2_rn(lo, hi);   // lo -> .x (low half)
    return *(uint32_t*)&h;
}

__device__ __forceinline__ uint32_t sa(const void* p) {
    return (uint32_t)__cvta_generic_to_shared(p);
}

__device__ __forceinline__ void ldsm4(uint32_t* r, uint32_t a) {
    asm volatile("ldmatrix.sync.aligned.m8n8.x4.shared.b16 {%0,%1,%2,%3}, [%4];"
        : "=r"(r[0]), "=r"(r[1]), "=r"(r[2]), "=r"(r[3]) : "r"(a));
}
__device__ __forceinline__ void ldsm2(uint32_t* r, uint32_t a) {
    asm volatile("ldmatrix.sync.aligned.m8n8.x2.shared.b16 {%0,%1}, [%2];"
        : "=r"(r[0]), "=r"(r[1]) : "r"(a));
}
__device__ __forceinline__ void ldsm2t(uint32_t* r, uint32_t a) {
    asm volatile("ldmatrix.sync.aligned.m8n8.x2.trans.shared.b16 {%0,%1}, [%2];"
        : "=r"(r[0]), "=r"(r[1]) : "r"(a));
}

__device__ __forceinline__ void mma_f16(float* c, const uint32_t* a,
                                        const uint32_t* b) {
    asm volatile(
        "mma.sync.aligned.m16n8k16.row.col.f32.f16.f16.f32 "
        "{%0,%1,%2,%3}, {%4,%5,%6,%7}, {%8,%9}, {%0,%1,%2,%3};"
        : "+f"(c[0]), "+f"(c[1]), "+f"(c[2]), "+f"(c[3])
        : "r"(a[0]), "r"(a[1]), "r"(a[2]), "r"(a[3]), "r"(b[0]), "r"(b[1]));
}

// ===========================================================================
// fp16 mma.sync GEMM: C[M,N] = A @ B + bias. CTA 128x128, 8 warps (2x4),
// warp 64x32, K-stage 32 (2 x k16).
// smem (f16, pitches in 4B words; all pitches mult of 4 words = 16B aligned):
//   As [m][32k]  pitch 20:  ldmatrix rows m*20 mod 32 = {0,20,8,28,16,4,24,12}
//                           -> 8 distinct 16B groups, conflict-free.
//   Bs [k][128n] pitch 68:  rows k*68 mod 32 = 4k -> distinct. x2.trans gives
//                           b-frags from row-major-k storage.
// MODE 0: A = x, scatter into g_q/g_k/g_v.  MODE 1: A = g_ctx, write Out.
// ===========================================================================
#define APW 20
#define BPW 68

template <int MODE>
__global__ __launch_bounds__(256, 2) void mma_gemm(const float* __restrict__ Ain,
                                                   const float* __restrict__ Bw,
                                                   const float* __restrict__ bias,
                                                   float* __restrict__ Out,
                                                   int N) {
    __shared__ __align__(16) uint32_t As[128 * APW];
    __shared__ __align__(16) uint32_t Bs[32 * BPW];

    const int tid = threadIdx.x;
    const int wid = tid >> 5, lane = tid & 31;
    const int warp_m = (wid >> 2) * 64;
    const int warp_n = (wid & 3) * 32;
    const int g = lane >> 2, t = lane & 3;
    const int bm = blockIdx.y * 128, bn = blockIdx.x * 128;

    const float* Ap = (MODE == 0) ? Ain : (const float*)g_ctx;

    float acc[4][4][4];
#pragma unroll
    for (int mf = 0; mf < 4; mf++)
#pragma unroll
        for (int nf = 0; nf < 4; nf++)
#pragma unroll
            for (int r = 0; r < 4; r++) acc[mf][nf][r] = 0.f;

    for (int k0 = 0; k0 < C_; k0 += 32) {
        __syncthreads();
#pragma unroll
        for (int r = 0; r < 4; r++) {
            int idx = tid + r * 256;
            int m = idx >> 3, kk = idx & 7;
            float4 v = *(const float4*)(Ap + (size_t)(bm + m) * C_ + k0 + kk * 4);
            uint32_t* d = &As[m * APW + kk * 2];
            d[0] = pack_h2(v.x, v.y);
            d[1] = pack_h2(v.z, v.w);
        }
#pragma unroll
        for (int r = 0; r < 4; r++) {
            int idx = tid + r * 256;
            int k = idx >> 5, n4 = idx & 31;
            float4 v = *(const float4*)(Bw + (size_t)(k0 + k) * N + bn + n4 * 4);
            uint32_t* d = &Bs[k * BPW + n4 * 2];
            d[0] = pack_h2(v.x, v.y);
            d[1] = pack_h2(v.z, v.w);
        }
        __syncthreads();

#pragma unroll
        for (int ks = 0; ks < 2; ks++) {
            uint32_t af[4][4], bf[4][2];
#pragma unroll
            for (int mf = 0; mf < 4; mf++)
                ldsm4(af[mf], sa(&As[(warp_m + mf * 16 + (lane & 15)) * APW +
                                     ks * 8 + (lane >> 4) * 4]));
#pragma unroll
            for (int nf = 0; nf < 4; nf++)
                ldsm2t(bf[nf], sa(&Bs[(ks * 16 + (lane & 15)) * BPW +
                                      warp_n / 2 + nf * 4]));
#pragma unroll
            for (int mf = 0; mf < 4; mf++)
#pragma unroll
                for (int nf = 0; nf < 4; nf++)
                    mma_f16(acc[mf][nf], af[mf], bf[nf]);
        }
    }

    // Epilogue (c-layout identical to tf32 version)
#pragma unroll
    for (int mf = 0; mf < 4; mf++) {
#pragma unroll
        for (int nf = 0; nf < 4; nf++) {
            const int n = bn + warp_n + nf * 8 + 2 * t;
            const float b0v = bias[n], b1v = bias[n + 1];
#pragma unroll
            for (int half = 0; half < 2; half++) {
                const int m = bm + warp_m + mf * 16 + g + half * 8;
                float v0 = acc[mf][nf][half * 2 + 0] + b0v;
                float v1 = acc[mf][nf][half * 2 + 1] + b1v;
                if (MODE == 0) {
                    int which = n >> 10;
                    int rem = n & 1023;
                    int h = rem >> 6, d = rem & 63;
                    int bi = m >> 11, tt = m & (T_ - 1);
                    float* dst = (which == 0) ? g_q : (which == 1) ? g_k : g_v;
                    *(float2*)&dst[(size_t)(((bi << 4) + h) * T_ + tt) * D_ + d] =
                        make_float2(v0, v1);
                } else {
                    *(float2*)&Out[(size_t)m * N + n] = make_float2(v0, v1);
                }
            }
        }
    }
}

// ===========================================================================
// fp16 mma.sync flash attention (R10 skeleton).
// CTA = (bh, 128 q), 8 warps x 16 q-rows, K-tile 64, k16 MMAs.
//   Qs/Ks/Vs f16 [row][64], pitch 36 words (144B = 9x16): ldmatrix rows
//   r*36 mod 32 = 4r -> conflict-free, 16B-aligned.
// QK: A = Q (ldsm4), B = K via non-trans x2 ([s][d] IS col-major for S=QK^T).
// PV: A = P packed DIRECTLY from sfr c-layout (k16 a-frag = same-lane pairs,
//     zero shuffles), B = V via x2.trans.
// ===========================================================================
#define QPW 36

__global__ __launch_bounds__(256, 2) void attn_mma() {
    __shared__ __align__(16) uint32_t Qs[128 * QPW];   // 18432 B
    __shared__ __align__(16) uint32_t Ks[64 * QPW];    //  9216 B
    __shared__ __align__(16) uint32_t Vs[64 * QPW];    //  9216 B

    const int tid = threadIdx.x;
    const int wid = tid >> 5, lane = tid & 31;
    const int g = lane >> 2, t = lane & 3;
    const int bh = blockIdx.y;
    const int q0 = blockIdx.x * 128;
    const int qrow = wid * 16;

    const float* Qg = g_q + (size_t)bh * T_ * D_;
    const float* Kg = g_k + (size_t)bh * T_ * D_;
    const float* Vg = g_v + (size_t)bh * T_ * D_;

    // Load Q tile (scaled by 1/8 — exact pow2), f16.
#pragma unroll
    for (int r = 0; r < 8; r++) {
        int idx = tid + r * 256;
        int m = idx >> 4, c4 = idx & 15;
        float4 v = *(const float4*)(Qg + (size_t)(q0 + m) * D_ + c4 * 4);
        uint32_t* d = &Qs[m * QPW + c4 * 2];
        d[0] = pack_h2(v.x * 0.125f, v.y * 0.125f);
        d[1] = pack_h2(v.z * 0.125f, v.w * 0.125f);
    }

    float m_i[2] = {-1e30f, -1e30f};
    float l_i[2] = {0.f, 0.f};
    float o[8][4];
#pragma unroll
    for (int nb = 0; nb < 8; nb++)
#pragma unroll
        for (int r = 0; r < 4; r++) o[nb][r] = 0.f;

    for (int kt = 0; kt < T_; kt += 64) {
        __syncthreads();   // prior tile consumed (and Q stores on iter 0)

#pragma unroll
        for (int r = 0; r < 4; r++) {
            int idx = tid + r * 256;
            int s = idx >> 4, c4 = idx & 15;
            float4 v = *(const float4*)(Kg + (size_t)(kt + s) * D_ + c4 * 4);
            uint32_t* d = &Ks[s * QPW + c4 * 2];
            d[0] = pack_h2(v.x, v.y);
            d[1] = pack_h2(v.z, v.w);
        }
#pragma unroll
        for (int r = 0; r < 4; r++) {
            int idx = tid + r * 256;
            int s = idx >> 4, c4 = idx & 15;
            float4 v = *(const float4*)(Vg + (size_t)(kt + s) * D_ + c4 * 4);
            uint32_t* d = &Vs[s * QPW + c4 * 2];
            d[0] = pack_h2(v.x, v.y);
            d[1] = pack_h2(v.z, v.w);
        }
        __syncthreads();

        // S = (Q/8) @ K^T  — warp 16x64, 4 k16 steps over d.
        float sfr[8][4];
#pragma unroll
        for (int nb = 0; nb < 8; nb++)
#pragma unroll
            for (int r = 0; r < 4; r++) sfr[nb][r] = 0.f;

#pragma unroll
        for (int ks = 0; ks < 4; ks++) {
            uint32_t af[4];
            ldsm4(af, sa(&Qs[(qrow + (lane & 15)) * QPW +
                             ks * 8 + (lane >> 4) * 4]));
#pragma unroll
            for (int nb = 0; nb < 8; nb++) {
                uint32_t bf[2];
                ldsm2(bf, sa(&Ks[(nb * 8 + (lane & 7)) * QPW +
                                 ks * 8 + ((lane >> 3) & 1) * 4]));
                mma_f16(sfr[nb], af, bf);
            }
        }

        // Online softmax per row-half (rows g, g+8), in-place exp on sfr.
#pragma unroll
        for (int half = 0; half < 2; half++) {
            const int h2 = half * 2;
            float mx = sfr[0][h2];
#pragma unroll
            for (int nb = 0; nb < 8; nb++) {
                mx = fmaxf(mx, sfr[nb][h2]);
                mx = fmaxf(mx, sfr[nb][h2 + 1]);
            }
            mx = fmaxf(mx, __shfl_xor_sync(0xffffffffu, mx, 1));
            mx = fmaxf(mx, __shfl_xor_sync(0xffffffffu, mx, 2));
            float mnew = fmaxf(m_i[half], mx);
            float corr = __expf(m_i[half] - mnew);
            m_i[half] = mnew;
            float ps = 0.f;
#pragma unroll
            for (int nb = 0; nb < 8; nb++) {
                float p0 = __expf(sfr[nb][h2] - mnew);
                float p1 = __expf(sfr[nb][h2 + 1] - mnew);
                sfr[nb][h2] = p0;
                sfr[nb][h2 + 1] = p1;
                ps += p0 + p1;
            }
            ps += __shfl_xor_sync(0xffffffffu, ps, 1);
            ps += __shfl_xor_sync(0xffffffffu, ps, 2);
            l_i[half] = l_i[half] * corr + ps;
#pragma unroll
            for (int nb = 0; nb < 8; nb++) {
                o[nb][h2] *= corr;
                o[nb][h2 + 1] *= corr;
            }
        }

        // O += P @ V — a-frags packed straight from sfr (same-lane identity).
#pragma unroll
        for (int ks = 0; ks < 4; ks++) {
            uint32_t af[4];
            af[0] = pack_h2(sfr[2 * ks][0], sfr[2 * ks][1]);
            af[1] = pack_h2(sfr[2 * ks][2], sfr[2 * ks][3]);
            af[2] = pack_h2(sfr[2 * ks + 1][0], sfr[2 * ks + 1][1]);
            af[3] = pack_h2(sfr[2 * ks + 1][2], sfr[2 * ks + 1][3]);
#pragma unroll
            for (int db = 0; db < 8; db++) {
                uint32_t bf[2];
                ldsm2t(bf, sa(&Vs[(ks * 16 + (lane & 15)) * QPW + db * 4]));
                mma_f16(o[db], af, bf);
            }
        }
    }

    // Normalize and write ctx[b][t][h*64+d]
    const int bi = bh >> 4, h = bh & 15;
    const float inv0 = 1.0f / l_i[0];
    const float inv1 = 1.0f / l_i[1];
#pragma unroll
    for (int db = 0; db < 8; db++) {
        const int d = db * 8 + 2 * t;
#pragma unroll
        for (int half = 0; half < 2; half++) {
            const float inv = half ? inv1 : inv0;
            const int tq = q0 + qrow + g + half * 8;
            float* dst = g_ctx + (size_t)(bi * T_ + tq) * C_ + h * D_ + d;
            *(float2*)dst = make_float2(o[db][half * 2] * inv,
                                        o[db][half * 2 + 1] * inv);
        }
    }
}

// ---------------------------------------------------------------------------
// Launch (plain grids — measured best in R10/R13/R15 comparison)
// ---------------------------------------------------------------------------
extern "C" void kernel_launch(void* const* d_in, const int* in_sizes, int n_in,
                              void* d_out, int out_size) {
    const float* x     = (const float*)d_in[0];
    const float* W_qkv = (const float*)d_in[1];
    const float* b_qkv = (const float*)d_in[2];
    const float* W_out = (const float*)d_in[3];
    const float* b_out = (const float*)d_in[4];
    float* out = (float*)d_out;

    (void)in_sizes; (void)n_in; (void)out_size;

    mma_gemm<0><<<dim3(3 * C_ / 128, M_ / 128), 256>>>(x, W_qkv, b_qkv,
                                                       nullptr, 3 * C_);
    attn_mma<<<dim3(T_ / 128, BH_), 256>>>();
    mma_gemm<1><<<dim3(C_ / 128, M_ / 128), 256>>>(nullptr, W_out, b_out,
                                                   out, C_);
}